// round 16
// baseline (speedup 1.0000x reference)
#include <cuda_runtime.h>

// Problem shapes are fixed by the dataset.
#define NPOI   50000
#define NNODES 100000
#define NEDGES 1000000
#define NDIST  512
#define DD     64
#define SLOTS  80   // per-node incidence bucket; degree ~ Poisson(20), P(>80) ~ 0

// Persistent grid: 148 SMs x 6 CTAs, co-residency guaranteed by
// __launch_bounds__(256, 6) -> the software grid barrier cannot deadlock.
#define NBLK 888
#define NTHR 256
#define NWARPS (NBLK * (NTHR / 32))

// Scratch (__device__ globals; no dynamic allocation allowed).
// x[n] == poi[sess[n]] exactly -> records carry the POI row id; the
// aggregation phase gathers straight from the (L2-resident, 12.8MB) poi
// input. Node scores factor through the POI row, so exp-dots are computed
// PER POI (coalesced) instead of per node (random gather).
__device__ float2 g_pexp[NPOI];         // {exp(poi[p].w_src), exp(poi[p].w_dst)}
__device__ int    g_cnt[NNODES];        // per-node incidence cursors
__device__ float  g_expb[NDIST];        // exp(delta_dis_embs[k] . w_src)
__device__ int2   g_adj[NNODES * SLOTS];// {poi_row(neighbor), bits(f32 weight)}
__device__ unsigned g_bar[4];           // barrier arrival counters
__device__ unsigned g_gen[4];           // barrier generations (monotone across replays)

// Software grid barrier. Read generation BEFORE arriving so a release between
// arrive and spin is always observed. Last arriver resets the counter and
// bumps the generation. Deterministic across graph replays.
__device__ __forceinline__ void grid_barrier(int i) {
    __syncthreads();
    if (threadIdx.x == 0) {
        __threadfence();
        unsigned base = ((volatile unsigned*)g_gen)[i];
        unsigned t = atomicAdd(&g_bar[i], 1u);
        if (t == NBLK - 1) {
            g_bar[i] = 0;
            __threadfence();
            atomicAdd(&g_gen[i], 1u);
        } else {
            while (((volatile unsigned*)g_gen)[i] == base) __nanosleep(100);
        }
        __threadfence();
    }
    __syncthreads();
}

// Emit both incidence records for one edge. P2 is atomic/scatter-bound
// (proven insensitive to gather count), so the small sess/pexp gathers here
// are hidden.  fwd @t: neighbor row ps, weight exp(asrc[t])*expb[k]
//              bwd @s: neighbor row pt, weight exp(adst[s])
__device__ __forceinline__ void emit(const int* __restrict__ sess, int s, int t, int k) {
    int ps = __ldg(&sess[s]);
    int pt = __ldg(&sess[t]);
    float2 es = __ldg(&g_pexp[ps]);
    float2 et = __ldg(&g_pexp[pt]);
    float ef = et.x * __ldg(&g_expb[k]);
    int pf = atomicAdd(&g_cnt[t], 1);
    int pb = atomicAdd(&g_cnt[s], 1);
    if (pf < SLOTS) g_adj[t * SLOTS + pf] = make_int2(ps, __float_as_int(ef));
    if (pb < SLOTS) g_adj[s * SLOTS + pb] = make_int2(pt, __float_as_int(es.y));
}

// ---------------------------------------------------------------------------
// Fused persistent kernel, two barriers:
//   A: per-block weight vectors (smem, redundant) + zero cursors + expb table
//      + PER-POI exp-dots (coalesced) — all grid-strided, no internal barrier.
//   barrier -> B (edge records, 4 edges/thread) -> barrier -> C (warp-per-node
//   aggregation, proven body at the LTS cap).
// Max-subtraction omitted (scores ~ N(0,2), softmax is shift-invariant; f32
// exp is safe).
// ---------------------------------------------------------------------------
__global__ void __launch_bounds__(NTHR, 6)
fused_all(const float* __restrict__ W,
          const float* __restrict__ asw,
          const float* __restrict__ adw,
          const float* __restrict__ dis,
          const float* __restrict__ poi,
          const int*   __restrict__ sess,
          const int*   __restrict__ esrc,
          const int*   __restrict__ edst,
          const int*   __restrict__ edist,
          float*       __restrict__ out) {
    __shared__ float ws[DD];   // w_src
    __shared__ float wd[DD];   // w_dst
    const int tid = threadIdx.x;
    const int gtid = blockIdx.x * NTHR + tid;

    // ---- A1: per-block weight vectors (redundant, cheap)
    if (tid < DD) {
        float s1 = 0.f, s2 = 0.f;
        #pragma unroll 8
        for (int f = 0; f < DD; f++) {
            float w = __ldg(&W[f * DD + tid]);
            s1 += __ldg(&asw[f]) * w;
            s2 += __ldg(&adw[f]) * w;
        }
        ws[tid] = s1;
        wd[tid] = s2;
    }
    __syncthreads();

    // ---- A2: zero cursors
    for (int n = gtid; n < NNODES; n += NBLK * NTHR) g_cnt[n] = 0;

    // ---- A3: expb table (512 rows)
    for (int k = gtid; k < NDIST; k += NBLK * NTHR) {
        const float* row = dis + k * DD;
        float s = 0.f;
        #pragma unroll 8
        for (int d = 0; d < DD; d++) s += row[d] * ws[d];
        g_expb[k] = __expf(s);
    }

    // ---- A4: per-POI exp-dots, coalesced. 16 lanes per POI row.
    {
        const float4* ws4 = (const float4*)ws;
        const float4* wd4 = (const float4*)wd;
        for (int gt = gtid; gt < NPOI * 16; gt += NBLK * NTHR) {
            int p = gt >> 4;
            int c = gt & 15;
            float4 v = __ldg(&((const float4*)poi)[(size_t)p * 16 + c]);
            float4 a = ws4[c];
            float4 d = wd4[c];
            float rs = v.x * a.x + v.y * a.y + v.z * a.z + v.w * a.w;
            float rd = v.x * d.x + v.y * d.y + v.z * d.z + v.w * d.w;
            #pragma unroll
            for (int o = 8; o >= 1; o >>= 1) {
                rs += __shfl_down_sync(0xffffffffu, rs, o, 16);
                rd += __shfl_down_sync(0xffffffffu, rd, o, 16);
            }
            if (c == 0) g_pexp[p] = make_float2(__expf(rs), __expf(rd));
        }
    }
    grid_barrier(0);

    // ---- B: four edges per step; append records for both directions.
    for (int i = gtid; i < NEDGES / 4; i += NBLK * NTHR) {
        int4 ss = __ldg(&((const int4*)esrc)[i]);
        int4 tt = __ldg(&((const int4*)edst)[i]);
        int4 kk = __ldg(&((const int4*)edist)[i]);
        emit(sess, ss.x, tt.x, kk.x);
        emit(sess, ss.y, tt.y, kk.y);
        emit(sess, ss.z, tt.z, kk.z);
        emit(sess, ss.w, tt.w, kk.w);
    }
    grid_barrier(1);

    // ---- C: warp-per-node aggregation (proven body, LTS-cap-bound). Two
    // half-warps; each batches FOUR records -> 8 independent gathers in
    // flight per warp. Denominator = sum of record weights.
    {
        int lane = tid & 31;
        int c = lane & 15;
        int h = lane >> 4;
        int warpid = gtid >> 5;
        const float4* x4 = (const float4*)poi;

        for (int w = warpid; w < NNODES; w += NWARPS) {
            int deg = g_cnt[w];
            if (deg > SLOTS) deg = SLOTS;
            const int2* adj = g_adj + (size_t)w * SLOTS;

            float4 acc = make_float4(0.f, 0.f, 0.f, 0.f);
            float  ssum = 0.f;

            int i = h;
            for (; i + 6 < deg; i += 8) {
                int2 r0 = __ldg(&adj[i]);
                int2 r1 = __ldg(&adj[i + 2]);
                int2 r2 = __ldg(&adj[i + 4]);
                int2 r3 = __ldg(&adj[i + 6]);
                float4 v0 = __ldg(&x4[(size_t)r0.x * 16 + c]);
                float4 v1 = __ldg(&x4[(size_t)r1.x * 16 + c]);
                float4 v2 = __ldg(&x4[(size_t)r2.x * 16 + c]);
                float4 v3 = __ldg(&x4[(size_t)r3.x * 16 + c]);
                float w0 = __int_as_float(r0.y);
                float w1 = __int_as_float(r1.y);
                float w2 = __int_as_float(r2.y);
                float w3 = __int_as_float(r3.y);
                ssum += (w0 + w1) + (w2 + w3);
                acc.x += w0 * v0.x + w1 * v1.x + w2 * v2.x + w3 * v3.x;
                acc.y += w0 * v0.y + w1 * v1.y + w2 * v2.y + w3 * v3.y;
                acc.z += w0 * v0.z + w1 * v1.z + w2 * v2.z + w3 * v3.z;
                acc.w += w0 * v0.w + w1 * v1.w + w2 * v2.w + w3 * v3.w;
            }
            for (; i < deg; i += 2) {
                int2 r = __ldg(&adj[i]);
                float wt = __int_as_float(r.y);
                float4 v = __ldg(&x4[(size_t)r.x * 16 + c]);
                ssum  += wt;
                acc.x += wt * v.x;
                acc.y += wt * v.y;
                acc.z += wt * v.z;
                acc.w += wt * v.w;
            }

            acc.x += __shfl_down_sync(0xffffffffu, acc.x, 16);
            acc.y += __shfl_down_sync(0xffffffffu, acc.y, 16);
            acc.z += __shfl_down_sync(0xffffffffu, acc.z, 16);
            acc.w += __shfl_down_sync(0xffffffffu, acc.w, 16);
            ssum  += __shfl_down_sync(0xffffffffu, ssum, 16);

            if (h == 0) {
                float inv = 1.f / (ssum + 1e-16f);
                acc.x *= inv; acc.y *= inv; acc.z *= inv; acc.w *= inv;
                ((float4*)out)[(size_t)w * 16 + c] = acc;
            }
        }
    }
}

// ---------------------------------------------------------------------------
extern "C" void kernel_launch(void* const* d_in, const int* in_sizes, int n_in,
                              void* d_out, int out_size) {
    const float* poi   = (const float*)d_in[0];  // [NPOI, D]
    const float* dis   = (const float*)d_in[1];  // [NDIST, D]
    const float* W     = (const float*)d_in[2];  // [D, D]
    const float* asw   = (const float*)d_in[3];  // [D]
    const float* adw   = (const float*)d_in[4];  // [D]
    const int*   sess  = (const int*)d_in[5];    // [NNODES]
    const int*   ei    = (const int*)d_in[6];    // [2, NEDGES]
    const int*   edist = (const int*)d_in[7];    // [NEDGES]
    float* out = (float*)d_out;                  // [NNODES, D]

    const int* esrc = ei;
    const int* edst = ei + NEDGES;

    fused_all<<<NBLK, NTHR>>>(W, asw, adw, dis, poi, sess, esrc, edst, edist, out);
}